// round 5
// baseline (speedup 1.0000x reference)
#include <cuda_runtime.h>
#include <math.h>

#define BB 4
#define CC 64
#define OO 64
#define HH 128
#define WW 128
#define OGG 2
#define CG 32
#define KK2 9
#define OMC 54           // 36 offset + 18 mask channels
#define SP (HH*WW)       // 16384

// scratch for offset+mask conv output: [B][54][H][W]
__device__ float g_offmask[BB * OMC * HH * WW];
// per-group partial outputs: [g][B][O][H][W]
__device__ float g_part[2][BB * OO * SP];

// ---------------------------------------------------------------------------
// Kernel 1: 3x3 conv producing 36 offset channels + 18 mask channels (sigmoid)
// 128 threads (16x8 pixel tile), input channels in chunks of 8 staged in smem.
// 3 CTAs/SM for latency hiding.
// ---------------------------------------------------------------------------
__global__ __launch_bounds__(128, 3) void conv_offmask_kernel(
    const float* __restrict__ x,
    const float* __restrict__ w_off, const float* __restrict__ b_off,
    const float* __restrict__ w_mask, const float* __restrict__ b_mask)
{
    __shared__ float xs[8][10][18];                 // 8 ch, 8 rows + halo, 16 cols + halo
    __shared__ __align__(16) float ws[8 * 9 * 56];  // [c][k][56] (54 padded to 56)

    const int tx = threadIdx.x;
    const int ty = threadIdx.y;
    const int tid = ty * 16 + tx;
    const int tileX0 = blockIdx.x * 16;
    const int tileY0 = blockIdx.y * 8;
    const int b = blockIdx.z;

    float acc[56];
#pragma unroll
    for (int i = 0; i < 56; i++) acc[i] = 0.f;

    for (int cc = 0; cc < CC; cc += 8) {
        __syncthreads();
        // stage x tile (10x18 halo) for 8 channels
        for (int i = tid; i < 8 * 10 * 18; i += 128) {
            int c = i / 180;
            int r = (i % 180) / 18;
            int col = i % 18;
            int gy = tileY0 + r - 1;
            int gx = tileX0 + col - 1;
            float v = 0.f;
            if (gy >= 0 && gy < HH && gx >= 0 && gx < WW)
                v = x[(((size_t)b * CC + cc + c) * HH + gy) * WW + gx];
            xs[c][r][col] = v;
        }
        // stage weights for 8 channels: ws[(c*9+k)*56 + o]
        for (int i = tid; i < 8 * 9 * 56; i += 128) {
            int c = i / (9 * 56);
            int k = (i / 56) % 9;
            int o = i % 56;
            float v = 0.f;
            if (o < 36)       v = w_off[(size_t)o * (CC * 9) + (cc + c) * 9 + k];
            else if (o < 54)  v = w_mask[(size_t)(o - 36) * (CC * 9) + (cc + c) * 9 + k];
            ws[i] = v;
        }
        __syncthreads();

#pragma unroll 1
        for (int c = 0; c < 8; c++) {
#pragma unroll
            for (int k = 0; k < 9; k++) {
                float xv = xs[c][ty + k / 3][tx + k % 3];
                const float4* wp = (const float4*)&ws[(c * 9 + k) * 56];
#pragma unroll
                for (int j = 0; j < 14; j++) {
                    float4 w4 = wp[j];
                    acc[4 * j + 0] += xv * w4.x;
                    acc[4 * j + 1] += xv * w4.y;
                    acc[4 * j + 2] += xv * w4.z;
                    acc[4 * j + 3] += xv * w4.w;
                }
            }
        }
    }

    const int y = tileY0 + ty;
    const int xcol = tileX0 + tx;
    float* outbase = g_offmask + ((size_t)b * OMC) * SP + y * WW + xcol;
#pragma unroll 1
    for (int o = 0; o < 54; o++) {
        float bias = (o < 36) ? b_off[o] : b_mask[o - 36];
        float v = acc[o] + bias;
        if (o >= 36) v = 1.f / (1.f + __expf(-v));
        outbase[(size_t)o * SP] = v;
    }
}

// ---------------------------------------------------------------------------
// Kernel 2: deformable conv, quad-split: gridDim.y = group g, gridDim.z = output half.
// 256 threads/CTA, 1 pixel/thread, acc[32]. Weights for (g, half) = 36.9 KB smem.
// 3 CTAs/SM -> 24 warps/SM while keeping ~117KB L1 for gather reuse.
// Partials per group written to g_part, summed by add_kernel.
// ---------------------------------------------------------------------------
__global__ __launch_bounds__(256, 3) void deform_kernel(
    const float* __restrict__ x,
    const float* __restrict__ w_main,
    float* __restrict__ part)
{
    __shared__ __align__(16) float wsm[CG * KK2 * 32];   // [(cl*9+k)*32 + oo]
    const int tid = threadIdx.x;
    const int g  = blockIdx.y;
    const int oh = blockIdx.z;

    // stage weights: wsm[(cl*9+k)*32 + oo] = w_main[(oh*32+oo)*576 + (g*32+cl)*9 + k]
    for (int i = tid; i < CG * KK2 * 32; i += 256) {
        int oo = i & 31;
        int ck = i >> 5;           // cl*9 + k
        wsm[i] = w_main[(size_t)(oh * 32 + oo) * (CC * KK2) + (g * CG) * KK2 + ck];
    }
    __syncthreads();

    const int p = blockIdx.x * 256 + tid;   // 0 .. B*H*W-1 (exact)
    const int b = p / SP;
    const int rem = p % SP;
    const int y = rem / WW;
    const int xc = rem % WW;

    float acc[32];
#pragma unroll
    for (int i = 0; i < 32; i++) acc[i] = 0.f;

    const float* offp = g_offmask + ((size_t)b * OMC) * SP + y * WW + xc;
    const float* xg = x + ((size_t)b * CC + g * CG) * SP;

#pragma unroll 1
    for (int k = 0; k < KK2; k++) {
        float oy = offp[(size_t)(g * 18 + k * 2 + 0) * SP];
        float ox = offp[(size_t)(g * 18 + k * 2 + 1) * SP];
        float m  = offp[(size_t)(36 + g * 9 + k) * SP];

        float py = oy + (float)(y - 1 + k / 3);
        float px = ox + (float)(xc - 1 + k % 3);
        float y0f = floorf(py);
        float x0f = floorf(px);
        float wy1 = py - y0f;
        float wx1 = px - x0f;
        float wy0 = 1.f - wy1;
        float wx0 = 1.f - wx1;
        int y0 = (int)y0f;
        int x0 = (int)x0f;
        int y1 = y0 + 1;
        int x1 = x0 + 1;
        float vy0 = (y0 >= 0 && y0 < HH) ? 1.f : 0.f;
        float vy1 = (y1 >= 0 && y1 < HH) ? 1.f : 0.f;
        float vx0 = (x0 >= 0 && x0 < WW) ? 1.f : 0.f;
        float vx1 = (x1 >= 0 && x1 < WW) ? 1.f : 0.f;
        int y0c = min(max(y0, 0), HH - 1);
        int y1c = min(max(y1, 0), HH - 1);
        int x0c = min(max(x0, 0), WW - 1);
        int x1c = min(max(x1, 0), WW - 1);

        float w00 = wy0 * wx0 * vy0 * vx0 * m;
        float w01 = wy0 * wx1 * vy0 * vx1 * m;
        float w10 = wy1 * wx0 * vy1 * vx0 * m;
        float w11 = wy1 * wx1 * vy1 * vx1 * m;

        int i00 = y0c * WW + x0c;
        int i01 = y0c * WW + x1c;
        int i10 = y1c * WW + x0c;
        int i11 = y1c * WW + x1c;

#pragma unroll
        for (int cc = 0; cc < CG; cc += 4) {
            // 16 independent loads batched for MLP
            float a0[4], a1[4], a2[4], a3[4];
#pragma unroll
            for (int j = 0; j < 4; j++) {
                const float* xch = xg + (size_t)(cc + j) * SP;
                a0[j] = xch[i00];
                a1[j] = xch[i01];
                a2[j] = xch[i10];
                a3[j] = xch[i11];
            }
#pragma unroll
            for (int j = 0; j < 4; j++) {
                float v = w00 * a0[j] + w01 * a1[j]
                        + w10 * a2[j] + w11 * a3[j];
                const float4* wp = (const float4*)&wsm[((cc + j) * KK2 + k) * 32];
#pragma unroll
                for (int q = 0; q < 8; q++) {
                    float4 w4 = wp[q];
                    acc[4 * q + 0] += v * w4.x;
                    acc[4 * q + 1] += v * w4.y;
                    acc[4 * q + 2] += v * w4.z;
                    acc[4 * q + 3] += v * w4.w;
                }
            }
        }
    }

    float* outp = part + (size_t)g * (BB * OO * SP)
                + ((size_t)b * OO + oh * 32) * SP + y * WW + xc;
#pragma unroll 1
    for (int o = 0; o < 32; o++)
        outp[(size_t)o * SP] = acc[o];
}

// ---------------------------------------------------------------------------
// Kernel 3: out = part[0] + part[1]  (float4 vectorized)
// ---------------------------------------------------------------------------
__global__ __launch_bounds__(256) void add_kernel(
    const float* __restrict__ part, float* __restrict__ out)
{
    int i = blockIdx.x * 256 + threadIdx.x;           // float4 index
    const float4* p0 = (const float4*)part;
    const float4* p1 = (const float4*)(part + (size_t)BB * OO * SP);
    float4 a = p0[i];
    float4 b = p1[i];
    float4 r;
    r.x = a.x + b.x; r.y = a.y + b.y; r.z = a.z + b.z; r.w = a.w + b.w;
    ((float4*)out)[i] = r;
}

// ---------------------------------------------------------------------------
extern "C" void kernel_launch(void* const* d_in, const int* in_sizes, int n_in,
                              void* d_out, int out_size)
{
    (void)in_sizes; (void)n_in; (void)out_size;
    const float* x      = (const float*)d_in[0];
    const float* w_main = (const float*)d_in[1];
    const float* w_off  = (const float*)d_in[2];
    const float* b_off  = (const float*)d_in[3];
    const float* w_mask = (const float*)d_in[4];
    const float* b_mask = (const float*)d_in[5];
    float* out = (float*)d_out;

    float* part;
    cudaGetSymbolAddress((void**)&part, g_part);

    dim3 grid1(WW / 16, HH / 8, BB);
    dim3 blk1(16, 8);
    conv_offmask_kernel<<<grid1, blk1>>>(x, w_off, b_off, w_mask, b_mask);

    dim3 grid2(BB * SP / 256, OGG, 2);
    deform_kernel<<<grid2, 256>>>(x, w_main, part);

    int n4 = BB * OO * SP / 4;
    add_kernel<<<n4 / 256, 256>>>(part, out);
}